// round 5
// baseline (speedup 1.0000x reference)
#include <cuda_runtime.h>
#include <cstdint>

#define NT 256
#define PX 136            // X smem row pitch (floats), conflict-free
#define XSTG (32 * PX)    // 4352
#define WSTG 4096         // 128ch x 32k per stage
#define STG  (XSTG + WSTG)  // 8448 floats per stage

// Pre-swizzled, rna-tf32, truncation-compensated weights.
// Per scale, per ntile(128ch), per ktile(32k):
//   idx = kkb*1024 + cg*128 + q*16 + tg*4 + i   (4096 floats / ktile)
//   ch = nt*128 + cg*16 + q + (i&1)*8 ; k = kt*32 + kkb*8 + tg + (i>>1)*4
// scale sizes: K*256 floats -> 65536 + 131072 + 262144 = 458752
__device__ float g_wswz[458752];

__device__ __forceinline__ void cp16(uint32_t dst, const float* src, bool pred) {
    asm volatile("cp.async.cg.shared.global [%0], [%1], 16, %2;\n"
                 :: "r"(dst), "l"(__cvta_generic_to_global(src)),
                    "r"(pred ? 16 : 0));
}

__device__ __forceinline__ void mma_tf32(float d[4], const uint32_t a[4],
                                         const uint32_t b[2], const float c[4]) {
    asm volatile(
        "mma.sync.aligned.m16n8k8.row.col.f32.tf32.tf32.f32 "
        "{%0,%1,%2,%3}, {%4,%5,%6,%7}, {%8,%9}, {%10,%11,%12,%13};"
        : "=f"(d[0]), "=f"(d[1]), "=f"(d[2]), "=f"(d[3])
        : "r"(a[0]), "r"(a[1]), "r"(a[2]), "r"(a[3]),
          "r"(b[0]), "r"(b[1]),
          "f"(c[0]), "f"(c[1]), "f"(c[2]), "f"(c[3]));
}

// ---------------- W prep: rna-tf32 + compensation + fragment swizzle ---------
__global__ void yolo_prep(const float* __restrict__ w0,
                          const float* __restrict__ w1,
                          const float* __restrict__ w2) {
    int idx = blockIdx.x * NT + threadIdx.x;
    if (idx >= 458752) return;
    const float* w; int K, base;
    if (idx < 65536)       { w = w0; K = 256;  base = 0; }
    else if (idx < 196608) { w = w1; K = 512;  base = 65536; }
    else                   { w = w2; K = 1024; base = 196608; }
    int r = idx - base;
    int nt = r / (K * 128); r -= nt * (K * 128);
    int kt  = r >> 12; r &= 4095;
    int kkb = r >> 10; r &= 1023;
    int cg  = r >> 7;  r &= 127;
    int q   = r >> 4;  r &= 15;
    int tg  = r >> 2;  int i = r & 3;
    int n = nt * 128 + cg * 16 + q + (i & 1) * 8;
    int k = kt * 32 + kkb * 8 + tg + (i >> 1) * 4;
    float v = 0.f;
    if (n < 255) {
        float x = w[n * K + k] * 1.000352f;   // compensate X-truncation shrink
        uint32_t u;
        asm("cvt.rna.tf32.f32 %0, %1;" : "=r"(u) : "f"(x));
        v = __uint_as_float(u);
    }
    g_wswz[idx] = v;
}

// ---------------- fused main: 3 scales, GEMM + decode ------------------------
// CTA tile: 128 channels x 128 spatial, BK=32. 8 warps = 2(ch) x 4(sp),
// warp tile 64ch x 32sp (4mi x 4ni). MMA: A=W (m16=ch), B=X (n8=spatial),
// spatial mapping m = sp*32 + q*4 + ni (makes B loads LDS.128).
__global__ __launch_bounds__(NT, 2)
void yolo_main(const float* __restrict__ p0, const float* __restrict__ p1,
               const float* __restrict__ p2,
               const float* __restrict__ bb0, const float* __restrict__ bb1,
               const float* __restrict__ bb2,
               const float* __restrict__ anchors, float* __restrict__ out) {
    extern __shared__ float smem[];   // 2 stages x STG floats
    __shared__ float sbias[128];

    const int tid = threadIdx.x;
    const int bx  = blockIdx.x;
    const int nt  = blockIdx.y;      // 0..1 (128-ch tiles)
    const int b   = blockIdx.z;

    const float* p; const float* bias; const float* anc;
    int K, S, nx, sh, mt, sbase, woff; float strd;
    if (bx < 50)      { p=p0; bias=bb0; anc=anchors;      K=256;  S=6400; nx=80; sh=6; mt=bx;    sbase=0;     woff=0;      strd=8.f;  }
    else if (bx < 63) { p=p1; bias=bb1; anc=anchors+6;    K=512;  S=1600; nx=40; sh=5; mt=bx-50; sbase=19200; woff=65536;  strd=16.f; }
    else              { p=p2; bias=bb2; anc=anchors+12;   K=1024; S=400;  nx=20; sh=4; mt=bx-63; sbase=24000; woff=196608; strd=32.f; }

    const int m0 = mt * 128;
    const int n0 = nt * 128;

    if (tid < 128) sbias[tid] = (n0 + tid < 255) ? bias[n0 + tid] : 0.f;

    // ---- async loaders ----
    const int  xm = (tid & 31) * 4;        // spatial (4 floats)
    const int  xk = tid >> 5;              // k row base (rows xk+8i)
    const bool xv = (m0 + xm) < S;
    const float* xg = p + (size_t)b * K * S + (size_t)xk * S + (m0 + xm);
    const float* wg = g_wswz + woff + nt * (K * 128) + tid * 16;

    const uint32_t sb = (uint32_t)__cvta_generic_to_shared(smem);
    const int nk = K >> 5;

    auto issue = [&](int tt, int ss) {
        const float* xs = xg + (size_t)(tt << 5) * S;
        const uint32_t xb = sb + (uint32_t)(ss * STG + xm) * 4u;
#pragma unroll
        for (int i = 0; i < 4; ++i)
            cp16(xb + (uint32_t)((xk + 8 * i) * PX) * 4u,
                 xs + (size_t)(8 * i) * S, xv);
        const float* ws = wg + tt * WSTG;
        const uint32_t wb = sb + (uint32_t)(ss * STG + XSTG + tid * 16) * 4u;
#pragma unroll
        for (int i = 0; i < 4; ++i)
            cp16(wb + 16u * i, ws + 4 * i, true);
        asm volatile("cp.async.commit_group;\n");
    };

    const int lane = tid & 31, wid = tid >> 5;
    const int c  = wid >> 2;   // channel half (0..1) -> 64ch
    const int sp = wid & 3;    // spatial quarter (0..3) -> 32sp
    const int q  = lane >> 2, tg = lane & 3;

    float acc[4][4][4];
#pragma unroll
    for (int mi = 0; mi < 4; ++mi)
#pragma unroll
        for (int ni = 0; ni < 4; ++ni)
#pragma unroll
            for (int r = 0; r < 4; ++r) acc[mi][ni][r] = 0.f;

    issue(0, 0);

    for (int t = 0; t < nk; ++t) {
        if (t + 1 < nk) {
            issue(t + 1, (t + 1) & 1);
            asm volatile("cp.async.wait_group 1;\n");
        } else {
            asm volatile("cp.async.wait_group 0;\n");
        }
        __syncthreads();

        const float* st = smem + (t & 1) * STG;
        const uint32_t* Xs = (const uint32_t*)st;
        const uint32_t* Ws = (const uint32_t*)(st + XSTG);

#pragma unroll
        for (int kkb = 0; kkb < 4; ++kkb) {
            uint4 av[4];
#pragma unroll
            for (int mi = 0; mi < 4; ++mi)
                av[mi] = *(const uint4*)(Ws + kkb * 1024 + (c * 4 + mi) * 128 +
                                         q * 16 + tg * 4);
            const uint4 b0 = *(const uint4*)(Xs + (kkb * 8 + tg) * PX + sp * 32 + q * 4);
            const uint4 b1 = *(const uint4*)(Xs + (kkb * 8 + tg + 4) * PX + sp * 32 + q * 4);
            const uint32_t bf[4][2] = {{b0.x, b1.x}, {b0.y, b1.y},
                                       {b0.z, b1.z}, {b0.w, b1.w}};
#pragma unroll
            for (int mi = 0; mi < 4; ++mi)
#pragma unroll
                for (int ni = 0; ni < 4; ++ni)
                    mma_tf32(acc[mi][ni], (const uint32_t*)&av[mi], bf[ni],
                             acc[mi][ni]);
        }
        __syncthreads();
    }

    // ---- fused epilogue: bias + sigmoid + YOLO decode ----
    const size_t ob = (size_t)b * 25200 + sbase;
#pragma unroll
    for (int mi = 0; mi < 4; ++mi)
#pragma unroll
        for (int ni = 0; ni < 4; ++ni)
#pragma unroll
            for (int r = 0; r < 4; ++r) {
                const int n = n0 + c * 64 + mi * 16 + q + ((r & 2) ? 8 : 0);
                const int m = m0 + sp * 32 + (tg * 2 + (r & 1)) * 4 + ni;
                if (n < 255 && m < S) {
                    const float v  = acc[mi][ni][r] + sbias[n - n0];
                    const float sg = 1.f / (1.f + __expf(-v));
                    const int a  = (n * 772) >> 16;   // n / 85 for n < 255
                    const int no = n - a * 85;
                    float ov;
                    if (no < 2) {
                        const int y = (int)(__umulhi((unsigned)m, 3435973837u) >> sh);
                        const int gc = (no == 0) ? (m - y * nx) : y;
                        ov = (2.f * sg + (float)gc - 0.5f) * strd;
                    } else if (no < 4) {
                        const float t2 = 2.f * sg;
                        ov = t2 * t2 * __ldg(anc + a * 2 + (no - 2));
                    } else {
                        ov = sg;
                    }
                    out[(ob + (size_t)a * S + m) * 85 + no] = ov;
                }
            }
}

extern "C" void kernel_launch(void* const* d_in, const int* in_sizes, int n_in,
                              void* d_out, int out_size) {
    const float* p0 = (const float*)d_in[0];
    const float* p1 = (const float*)d_in[1];
    const float* p2 = (const float*)d_in[2];
    const float* w0 = (const float*)d_in[3];
    const float* b0 = (const float*)d_in[4];
    const float* w1 = (const float*)d_in[5];
    const float* b1 = (const float*)d_in[6];
    const float* w2 = (const float*)d_in[7];
    const float* b2 = (const float*)d_in[8];
    const float* anc = (const float*)d_in[9];
    float* out = (float*)d_out;

    cudaFuncSetAttribute(yolo_main, cudaFuncAttributeMaxDynamicSharedMemorySize,
                         2 * STG * 4);

    yolo_prep<<<1792, NT>>>(w0, w1, w2);
    // m-tiles: 50 (80x80) + 13 (40x40) + 4 (20x20) = 67 ; n-tiles: 2 x 128ch
    yolo_main<<<dim3(67, 2, 16), NT, 2 * STG * 4>>>(p0, p1, p2, b0, b1, b2,
                                                    anc, out);
}

// round 6
// speedup vs baseline: 1.2189x; 1.2189x over previous
#include <cuda_runtime.h>
#include <cstdint>

#define NT 256
#define PX 136            // X smem row pitch (floats), conflict-free
#define XSTG (32 * PX)    // 4352
#define WSTG 2048         // 64ch x 32k per stage
#define STG  (XSTG + WSTG)  // 6400 floats per stage

// Pre-swizzled, rna-tf32, truncation-compensated weights.
// Per scale, per ntile(64ch), per ktile(32k, 2048 floats):
//   idx = kkb*512 + cg*128 + g*16 + tg*4 + i
//   ch = nt*64 + cg*16 + g + (i&1)*8 ;  k = kt*32 + kkb*8 + tg + (i>>1)*4
// scale sizes: K*256 floats -> 65536 + 131072 + 262144 = 458752
__device__ float g_wswz[458752];

__device__ __forceinline__ void cp16(uint32_t dst, const float* src, bool pred) {
    asm volatile("cp.async.cg.shared.global [%0], [%1], 16, %2;\n"
                 :: "r"(dst), "l"(__cvta_generic_to_global(src)),
                    "r"(pred ? 16 : 0));
}

__device__ __forceinline__ void mma_tf32(float d[4], const uint32_t a[4],
                                         const uint32_t b[2], const float c[4]) {
    asm volatile(
        "mma.sync.aligned.m16n8k8.row.col.f32.tf32.tf32.f32 "
        "{%0,%1,%2,%3}, {%4,%5,%6,%7}, {%8,%9}, {%10,%11,%12,%13};"
        : "=f"(d[0]), "=f"(d[1]), "=f"(d[2]), "=f"(d[3])
        : "r"(a[0]), "r"(a[1]), "r"(a[2]), "r"(a[3]),
          "r"(b[0]), "r"(b[1]),
          "f"(c[0]), "f"(c[1]), "f"(c[2]), "f"(c[3]));
}

// ---------------- W prep: rna-tf32 + compensation + fragment swizzle ---------
__global__ void yolo_prep(const float* __restrict__ w0,
                          const float* __restrict__ w1,
                          const float* __restrict__ w2) {
    int idx = blockIdx.x * NT + threadIdx.x;
    if (idx >= 458752) return;
    const float* w; int K, base;
    if (idx < 65536)       { w = w0; K = 256;  base = 0; }
    else if (idx < 196608) { w = w1; K = 512;  base = 65536; }
    else                   { w = w2; K = 1024; base = 196608; }
    int r = idx - base;
    int nt = r / (K * 64); r -= nt * (K * 64);
    int kt  = r >> 11; r &= 2047;
    int kkb = r >> 9;  r &= 511;
    int cg  = r >> 7;  r &= 127;
    int g   = r >> 4;  r &= 15;
    int tg  = r >> 2;  int i = r & 3;
    int n = nt * 64 + cg * 16 + g + (i & 1) * 8;
    int k = kt * 32 + kkb * 8 + tg + (i >> 1) * 4;
    float v = 0.f;
    if (n < 255) {
        float x = w[n * K + k] * 1.000352f;   // compensate X-truncation shrink
        uint32_t u;
        asm("cvt.rna.tf32.f32 %0, %1;" : "=r"(u) : "f"(x));
        v = __uint_as_float(u);
    }
    g_wswz[idx] = v;
}

// ---------------- fused main: 3 scales, GEMM + decode ------------------------
// CTA tile: 64 channels x 128 spatial, BK=32. 8 warps = 2(ch) x 4(sp),
// warp tile 32ch x 32sp (2mi x 4ni). MMA: A=W (m16=ch), B=X (n8=spatial),
// spatial mapping m = sp*32 + g*4 + ni so B loads are LDS.128.
__global__ __launch_bounds__(NT, 3)
void yolo_main(const float* __restrict__ p0, const float* __restrict__ p1,
               const float* __restrict__ p2,
               const float* __restrict__ bb0, const float* __restrict__ bb1,
               const float* __restrict__ bb2,
               const float* __restrict__ anchors, float* __restrict__ out) {
    extern __shared__ float smem[];   // 2 stages x STG floats
    __shared__ float sbias[64];

    const int tid = threadIdx.x;
    const int bx  = blockIdx.x;
    const int nt  = blockIdx.y;      // 0..3 (64-ch tiles)
    const int b   = blockIdx.z;

    const float* p; const float* bias; const float* anc;
    int K, S, nx, sh, mt, sbase, woff; float strd;
    if (bx < 50)      { p=p0; bias=bb0; anc=anchors;      K=256;  S=6400; nx=80; sh=6; mt=bx;    sbase=0;     woff=0;      strd=8.f;  }
    else if (bx < 63) { p=p1; bias=bb1; anc=anchors+6;    K=512;  S=1600; nx=40; sh=5; mt=bx-50; sbase=19200; woff=65536;  strd=16.f; }
    else              { p=p2; bias=bb2; anc=anchors+12;   K=1024; S=400;  nx=20; sh=4; mt=bx-63; sbase=24000; woff=196608; strd=32.f; }

    const int m0 = mt * 128;
    const int n0 = nt * 64;

    if (tid < 64) sbias[tid] = (n0 + tid < 255) ? bias[n0 + tid] : 0.f;

    // ---- async loaders ----
    const int  xm = (tid & 31) * 4;        // spatial (4 floats)
    const int  xk = tid >> 5;              // k row base (rows xk+8i)
    const bool xv = (m0 + xm) < S;
    const float* xg = p + (size_t)b * K * S + (size_t)xk * S + (m0 + xm);
    const float* wg = g_wswz + woff + nt * (K * 64) + tid * 8;

    const uint32_t sb = (uint32_t)__cvta_generic_to_shared(smem);
    const int nk = K >> 5;

    auto issue = [&](int tt, int ss) {
        const float* xs = xg + (size_t)(tt << 5) * S;
        const uint32_t xb = sb + (uint32_t)(ss * STG + xm) * 4u;
#pragma unroll
        for (int i = 0; i < 4; ++i)
            cp16(xb + (uint32_t)((xk + 8 * i) * PX) * 4u,
                 xs + (size_t)(8 * i) * S, xv);
        const float* ws = wg + tt * WSTG;
        const uint32_t wb = sb + (uint32_t)(ss * STG + XSTG + tid * 8) * 4u;
        cp16(wb,      ws,     true);
        cp16(wb + 16, ws + 4, true);
        asm volatile("cp.async.commit_group;\n");
    };

    const int lane = tid & 31, wid = tid >> 5;
    const int c  = wid >> 2;   // channel half (0..1) -> 32ch
    const int sp = wid & 3;    // spatial quarter (0..3) -> 32sp
    const int g  = lane >> 2, tg = lane & 3;

    float acc[2][4][4];
#pragma unroll
    for (int mi = 0; mi < 2; ++mi)
#pragma unroll
        for (int ni = 0; ni < 4; ++ni)
#pragma unroll
            for (int r = 0; r < 4; ++r) acc[mi][ni][r] = 0.f;

    issue(0, 0);

    for (int t = 0; t < nk; ++t) {
        if (t + 1 < nk) {
            issue(t + 1, (t + 1) & 1);
            asm volatile("cp.async.wait_group 1;\n");
        } else {
            asm volatile("cp.async.wait_group 0;\n");
        }
        __syncthreads();

        const float* st = smem + (t & 1) * STG;
        const uint32_t* Xs = (const uint32_t*)st;
        const uint32_t* Ws = (const uint32_t*)(st + XSTG);

#pragma unroll
        for (int kkb = 0; kkb < 4; ++kkb) {
            uint4 av[2];
#pragma unroll
            for (int mi = 0; mi < 2; ++mi)
                av[mi] = *(const uint4*)(Ws + kkb * 512 + (c * 2 + mi) * 128 +
                                         g * 16 + tg * 4);
            const uint4 b0 = *(const uint4*)(Xs + (kkb * 8 + tg) * PX + sp * 32 + g * 4);
            const uint4 b1 = *(const uint4*)(Xs + (kkb * 8 + tg + 4) * PX + sp * 32 + g * 4);
            const uint32_t bf[4][2] = {{b0.x, b1.x}, {b0.y, b1.y},
                                       {b0.z, b1.z}, {b0.w, b1.w}};
#pragma unroll
            for (int mi = 0; mi < 2; ++mi)
#pragma unroll
                for (int ni = 0; ni < 4; ++ni)
                    mma_tf32(acc[mi][ni], (const uint32_t*)&av[mi], bf[ni],
                             acc[mi][ni]);
        }
        __syncthreads();
    }

    // ---- fused epilogue: bias + sigmoid + YOLO decode ----
    const size_t ob = (size_t)b * 25200 + sbase;
#pragma unroll
    for (int mi = 0; mi < 2; ++mi)
#pragma unroll
        for (int ni = 0; ni < 4; ++ni)
#pragma unroll
            for (int r = 0; r < 4; ++r) {
                const int n = n0 + c * 32 + mi * 16 + g + ((r & 2) ? 8 : 0);
                const int m = m0 + sp * 32 + (tg * 2 + (r & 1)) * 4 + ni;
                if (n < 255 && m < S) {
                    const float v  = acc[mi][ni][r] + sbias[n - n0];
                    const float sg = 1.f / (1.f + __expf(-v));
                    const int a  = (n * 772) >> 16;   // n / 85 for n < 255
                    const int no = n - a * 85;
                    float ov;
                    if (no < 2) {
                        const int y = (int)(__umulhi((unsigned)m, 3435973837u) >> sh);
                        const int gc = (no == 0) ? (m - y * nx) : y;
                        ov = (2.f * sg + (float)gc - 0.5f) * strd;
                    } else if (no < 4) {
                        const float t2 = 2.f * sg;
                        ov = t2 * t2 * __ldg(anc + a * 2 + (no - 2));
                    } else {
                        ov = sg;
                    }
                    out[(ob + (size_t)a * S + m) * 85 + no] = ov;
                }
            }
}

extern "C" void kernel_launch(void* const* d_in, const int* in_sizes, int n_in,
                              void* d_out, int out_size) {
    const float* p0 = (const float*)d_in[0];
    const float* p1 = (const float*)d_in[1];
    const float* p2 = (const float*)d_in[2];
    const float* w0 = (const float*)d_in[3];
    const float* b0 = (const float*)d_in[4];
    const float* w1 = (const float*)d_in[5];
    const float* b1 = (const float*)d_in[6];
    const float* w2 = (const float*)d_in[7];
    const float* b2 = (const float*)d_in[8];
    const float* anc = (const float*)d_in[9];
    float* out = (float*)d_out;

    cudaFuncSetAttribute(yolo_main, cudaFuncAttributeMaxDynamicSharedMemorySize,
                         2 * STG * 4);

    yolo_prep<<<1792, NT>>>(w0, w1, w2);
    // m-tiles: 50 (80x80) + 13 (40x40) + 4 (20x20) = 67 ; n-tiles: 4 x 64ch
    yolo_main<<<dim3(67, 4, 16), NT, 2 * STG * 4>>>(p0, p1, p2, b0, b1, b2,
                                                    anc, out);
}